// round 16
// baseline (speedup 1.0000x reference)
#include <cuda_runtime.h>
#include <math.h>

#define IMG_H   128
#define IMG_W   128
#define NB      4
#define IMG     (IMG_H * IMG_W)          // 16384
#define NPIX    (NB * IMG)               // 65536
#define STRIPS  16
#define SROWS   8                        // output rows per strip
#define GBLK    (NB * STRIPS)            // 64 blocks (4 img x 16 strips)
#define THREADS 256
#define NWARP   (THREADS / 32)
#define ST      128                      // smem row stride
#define MAXR    16                       // 8 + 4 halo each side
#define FULLM   0xffffffffu

// Packed accumulator layout (same for smem warp-merge and global block-merge):
//   bits [57,64) : arrival count (warps: max 8; blocks: max 64)
//   bits [20,57) : span_q  = round(span * 2^14)   (total ~2^31, fits 37 bits)
//   bits [ 0,20) : wmse_q  = round(wmse * 2^2)    (total ~2^20)
#define SPAN_SH   20
#define ARR_SH    57
#define SPAN_MASK ((1ULL << 37) - 1ULL)
#define WM_MASK   ((1ULL << 20) - 1ULL)
#define SPAN_SCALE 16384.0f              // 2^14
#define WM_SCALE   4.0f                  // 2^2

// Global accumulator (zero-init; finisher resets in place each launch).
__device__ unsigned long long g_acc;

__device__ __forceinline__ void st_rlx64(unsigned long long* p, unsigned long long v) {
    asm volatile("st.relaxed.gpu.global.b64 [%0], %1;" :: "l"(p), "l"(v) : "memory");
}

// Horizontal 9-tap box sums for 4 pixels/lane, entirely in registers.
__device__ __forceinline__ float4 hbox_shfl(float4 v, int lane) {
    float4 p, n;
    p.x = __shfl_up_sync(FULLM, v.x, 1);
    p.y = __shfl_up_sync(FULLM, v.y, 1);
    p.z = __shfl_up_sync(FULLM, v.z, 1);
    p.w = __shfl_up_sync(FULLM, v.w, 1);
    n.x = __shfl_down_sync(FULLM, v.x, 1);
    n.y = __shfl_down_sync(FULLM, v.y, 1);
    n.z = __shfl_down_sync(FULLM, v.z, 1);
    n.w = __shfl_down_sync(FULLM, v.w, 1);
    if (lane == 0)  { p.x = p.y = p.z = p.w = 0.0f; }
    if (lane == 31) { n.x = n.y = n.z = n.w = 0.0f; }
    float4 s;
    s.x = ((p.x + p.y) + (p.z + p.w)) + ((v.x + v.y) + (v.z + v.w)) + n.x;
    s.y = s.x - p.x + n.y;
    s.z = s.y - p.y + n.z;
    s.w = s.z - p.z + n.w;
    return s;
}

__device__ __forceinline__ float wmse_px4(float4 pv, float4 tv) {
    float acc = 0.0f;
    float pp[4] = {pv.x, pv.y, pv.z, pv.w};
    float tt[4] = {tv.x, tv.y, tv.z, tv.w};
    #pragma unroll
    for (int k = 0; k < 4; ++k) {
        float t = tt[k];
        float w = 1.0f;
        if (t >= 0.5f)  w = 2.0f;
        if (t >= 2.0f)  w = 5.0f;
        if (t >= 5.0f)  w = 10.0f;
        if (t >= 10.0f) w = 30.0f;
        float d = pp[k] - t;
        acc += w * d * d;
    }
    return acc;
}

__global__ void __launch_bounds__(THREADS, 1)
fused_loss(const float* __restrict__ pred, const float* __restrict__ tgt,
           float* __restrict__ out) {
    __shared__ float imgA[MAXR * ST];
    __shared__ float imgB[MAXR * ST];
    __shared__ float hsA [MAXR * ST];
    __shared__ float hsB [MAXR * ST];
    __shared__ unsigned long long s_acc;   // packed warp merge

    const int tid  = threadIdx.x;
    const int lane = tid & 31;
    const int wid  = tid >> 5;
    const int b    = blockIdx.x;
    const int im   = b >> 4;
    const int strip = b & 15;

    if (tid == 0) s_acc = 0ULL;

    const int y0 = strip * SROWS;
    const int lo = max(0, y0 - 4);
    const int hi = min(IMG_H, y0 + SROWS + 4);
    const int nrows = hi - lo;

    // ---- fused load + horizontal filter (regs/shuffles) + wmse ----------
    float wsum = 0.0f;      // per-thread; reduced only at the very end
    {
        const float4* p4 = (const float4*)(pred + (im * IMG + lo * IMG_W));
        const float4* t4 = (const float4*)(tgt  + (im * IMG + lo * IMG_W));
        const int r1 = wid;
        const int r2 = wid + 8;
        const bool ok2 = (r2 < nrows);          // warp-uniform

        float4 pv1 = p4[r1 * 32 + lane];
        float4 tv1 = t4[r1 * 32 + lane];
        float4 pv2, tv2;
        if (ok2) { pv2 = p4[r2 * 32 + lane]; tv2 = t4[r2 * 32 + lane]; }

        {
            float4 sA = hbox_shfl(pv1, lane);
            float4 sB = hbox_shfl(tv1, lane);
            ((float4*)(hsA + r1 * ST))[lane] = sA;
            ((float4*)(hsB + r1 * ST))[lane] = sB;
            const int gy = lo + r1;
            if (gy >= y0 && gy < y0 + SROWS) {   // own row: img + wmse
                ((float4*)(imgA + r1 * ST))[lane] = pv1;
                ((float4*)(imgB + r1 * ST))[lane] = tv1;
                wsum += wmse_px4(pv1, tv1);
            }
        }
        if (ok2) {
            float4 sA = hbox_shfl(pv2, lane);
            float4 sB = hbox_shfl(tv2, lane);
            ((float4*)(hsA + r2 * ST))[lane] = sA;
            ((float4*)(hsB + r2 * ST))[lane] = sB;
            const int gy = lo + r2;
            if (gy >= y0 && gy < y0 + SROWS) {
                ((float4*)(imgA + r2 * ST))[lane] = pv2;
                ((float4*)(imgB + r2 * ST))[lane] = tv2;
                wsum += wmse_px4(pv2, tv2);
            }
        }
    }
    __syncthreads();     // hs/img + s_acc init visible (ONLY barrier)

    // ---- vertical sliding sums + span = sum |distP - distT| --------------
    const int x   = tid & 127;
    const int seg = tid >> 7;
    const int yb  = y0 + seg * 4;
    const int cx  = min(x + 4, IMG_W - 1) - max(x - 4, 0) + 1;

    float span = 0.0f;
    {
        float sA = 0.0f, sB = 0.0f;
        const int wlo = max(0, yb - 4), whi = min(IMG_H - 1, yb + 4);
        for (int yy = wlo; yy <= whi; ++yy) {
            sA += hsA[(yy - lo) * ST + x];
            sB += hsB[(yy - lo) * ST + x];
        }
        #pragma unroll
        for (int k = 0; k < 4; ++k) {
            const int y  = yb + k;
            const int cy = min(y + 4, IMG_H - 1) - max(y - 4, 0) + 1;
            const float inv = __fdividef(1.0f, (float)(cx * cy));
            const float da = imgA[(y - lo) * ST + x] - sA * inv;
            const float db = imgB[(y - lo) * ST + x] - sB * inv;
            span += fabsf(da - db);
            if (k < 3) {
                if (y + 5 < IMG_H) { sA += hsA[(y + 5 - lo) * ST + x];
                                     sB += hsB[(y + 5 - lo) * ST + x]; }
                if (y - 4 >= 0)    { sA -= hsA[(y - 4 - lo) * ST + x];
                                     sB -= hsB[(y - 4 - lo) * ST + x]; }
            }
        }
    }

    // ---- per-thread fixed-point quantize + hardware REDUX (1 instr each) --
    const unsigned sp_t = (unsigned)__float2int_rn(span * SPAN_SCALE);
    const unsigned wm_t = (unsigned)__float2int_rn(wsum * WM_SCALE);
    const unsigned sp_w = __reduce_add_sync(FULLM, sp_t);   // warp span_q
    const unsigned wm_w = __reduce_add_sync(FULLM, wm_t);   // warp wmse_q

    // ---- packed warp merge in smem; last warp fires the global atomic -----
    if (lane == 0) {
        const unsigned long long add =
            (1ULL << ARR_SH) | ((unsigned long long)sp_w << SPAN_SH)
                             |  (unsigned long long)wm_w;
        const unsigned long long prev = atomicAdd(&s_acc, add);
        if ((prev >> ARR_SH) == (unsigned long long)(NWARP - 1)) {
            // block totals arrived in the same transaction
            const unsigned long long tot = prev + add;
            const unsigned long long sp_blk = (tot >> SPAN_SH) & SPAN_MASK;
            const unsigned long long wm_blk = tot & WM_MASK;
            const unsigned long long gadd =
                (1ULL << ARR_SH) | (sp_blk << SPAN_SH) | wm_blk;
            const unsigned long long gprev = atomicAdd(&g_acc, gadd);
            if ((gprev >> ARR_SH) == (unsigned long long)(GBLK - 1)) {
                const unsigned long long gtot = gprev + gadd;
                st_rlx64(&g_acc, 0ULL);          // reset for next launch
                const double sp_tot =
                    (double)((gtot >> SPAN_SH) & SPAN_MASK) / (double)SPAN_SCALE;
                const double wm_tot =
                    (double)(gtot & WM_MASK) / (double)WM_SCALE;
                const double crps = sp_tot / (double)NPIX;
                const double wmse = wm_tot / (double)NPIX;
                out[0] = (float)(1e-4 * wmse + crps);
            }
        }
    }
}

extern "C" void kernel_launch(void* const* d_in, const int* in_sizes, int n_in,
                              void* d_out, int out_size) {
    (void)in_sizes; (void)n_in; (void)out_size;
    const float* pred = (const float*)d_in[0];
    const float* tgt  = (const float*)d_in[1];
    float* out = (float*)d_out;

    fused_loss<<<GBLK, THREADS>>>(pred, tgt, out);
}

// round 17
// speedup vs baseline: 1.0433x; 1.0433x over previous
#include <cuda_runtime.h>
#include <math.h>

#define IMG_H   128
#define IMG_W   128
#define NB      4
#define IMG     (IMG_H * IMG_W)          // 16384
#define NPIX    (NB * IMG)               // 65536
#define STRIPS  16
#define SROWS   8                        // output rows per strip
#define GBLK    (NB * STRIPS)            // 64 blocks (4 img x 16 strips)
#define THREADS 256
#define NWARP   (THREADS / 32)
#define ST      128                      // smem row stride (in float2 elems)
#define MAXR    16                       // 8 + 4 halo each side
#define FULLM   0xffffffffu

// Packed accumulator layout (same for smem warp-merge and global block-merge):
//   bits [57,64) : arrival count (warps: max 8; blocks: max 64)
//   bits [20,57) : span_q  = round(span * 2^14)
//   bits [ 0,20) : wmse_q  = round(wmse * 2^2)
#define SPAN_SH   20
#define ARR_SH    57
#define SPAN_MASK ((1ULL << 37) - 1ULL)
#define WM_MASK   ((1ULL << 20) - 1ULL)
#define SPAN_SCALE 16384.0               // 2^14
#define WM_SCALE   4.0                   // 2^2

// Global accumulator (zero-init; finisher resets in place each launch).
__device__ unsigned long long g_acc;

__device__ __forceinline__ void st_rlx64(unsigned long long* p, unsigned long long v) {
    asm volatile("st.relaxed.gpu.global.b64 [%0], %1;" :: "l"(p), "l"(v) : "memory");
}

// Horizontal 9-tap box sums for 4 pixels/lane, entirely in registers.
__device__ __forceinline__ float4 hbox_shfl(float4 v, int lane) {
    float4 p, n;
    p.x = __shfl_up_sync(FULLM, v.x, 1);
    p.y = __shfl_up_sync(FULLM, v.y, 1);
    p.z = __shfl_up_sync(FULLM, v.z, 1);
    p.w = __shfl_up_sync(FULLM, v.w, 1);
    n.x = __shfl_down_sync(FULLM, v.x, 1);
    n.y = __shfl_down_sync(FULLM, v.y, 1);
    n.z = __shfl_down_sync(FULLM, v.z, 1);
    n.w = __shfl_down_sync(FULLM, v.w, 1);
    if (lane == 0)  { p.x = p.y = p.z = p.w = 0.0f; }
    if (lane == 31) { n.x = n.y = n.z = n.w = 0.0f; }
    float4 s;
    s.x = ((p.x + p.y) + (p.z + p.w)) + ((v.x + v.y) + (v.z + v.w)) + n.x;
    s.y = s.x - p.x + n.y;
    s.z = s.y - p.y + n.z;
    s.w = s.z - p.z + n.w;
    return s;
}

__device__ __forceinline__ float wmse_px4(float4 pv, float4 tv) {
    float acc = 0.0f;
    float pp[4] = {pv.x, pv.y, pv.z, pv.w};
    float tt[4] = {tv.x, tv.y, tv.z, tv.w};
    #pragma unroll
    for (int k = 0; k < 4; ++k) {
        float t = tt[k];
        float w = 1.0f;
        if (t >= 0.5f)  w = 2.0f;
        if (t >= 2.0f)  w = 5.0f;
        if (t >= 5.0f)  w = 10.0f;
        if (t >= 10.0f) w = 30.0f;
        float d = pp[k] - t;
        acc += w * d * d;
    }
    return acc;
}

__global__ void __launch_bounds__(THREADS, 1)
fused_loss(const float* __restrict__ pred, const float* __restrict__ tgt,
           float* __restrict__ out) {
    // Interleaved {pred, tgt} pairs: one LDS.64 serves both tensors.
    __shared__ float2 img2[MAXR * ST];
    __shared__ float2 hs2 [MAXR * ST];
    __shared__ float  wws[NWARP];
    __shared__ float  wsp[NWARP];
    __shared__ unsigned long long s_acc;   // packed warp merge

    const int tid  = threadIdx.x;
    const int lane = tid & 31;
    const int wid  = tid >> 5;
    const int b    = blockIdx.x;
    const int im   = b >> 4;
    const int strip = b & 15;

    if (tid == 0) s_acc = 0ULL;

    const int y0 = strip * SROWS;
    const int lo = max(0, y0 - 4);
    const int hi = min(IMG_H, y0 + SROWS + 4);
    const int nrows = hi - lo;

    // ---- fused load + horizontal filter (regs/shuffles) + wmse ----------
    float wsum = 0.0f;
    {
        const float4* p4 = (const float4*)(pred + (im * IMG + lo * IMG_W));
        const float4* t4 = (const float4*)(tgt  + (im * IMG + lo * IMG_W));
        const int r1 = wid;
        const int r2 = wid + 8;
        const bool ok2 = (r2 < nrows);          // warp-uniform

        float4 pv1 = p4[r1 * 32 + lane];
        float4 tv1 = t4[r1 * 32 + lane];
        float4 pv2, tv2;
        if (ok2) { pv2 = p4[r2 * 32 + lane]; tv2 = t4[r2 * 32 + lane]; }

        {
            float4 sA = hbox_shfl(pv1, lane);
            float4 sB = hbox_shfl(tv1, lane);
            float4* hrow = (float4*)(hs2 + r1 * ST);
            hrow[2 * lane]     = make_float4(sA.x, sB.x, sA.y, sB.y);
            hrow[2 * lane + 1] = make_float4(sA.z, sB.z, sA.w, sB.w);
            const int gy = lo + r1;
            if (gy >= y0 && gy < y0 + SROWS) {   // own row: img + wmse
                float4* irow = (float4*)(img2 + r1 * ST);
                irow[2 * lane]     = make_float4(pv1.x, tv1.x, pv1.y, tv1.y);
                irow[2 * lane + 1] = make_float4(pv1.z, tv1.z, pv1.w, tv1.w);
                wsum += wmse_px4(pv1, tv1);
            }
        }
        if (ok2) {
            float4 sA = hbox_shfl(pv2, lane);
            float4 sB = hbox_shfl(tv2, lane);
            float4* hrow = (float4*)(hs2 + r2 * ST);
            hrow[2 * lane]     = make_float4(sA.x, sB.x, sA.y, sB.y);
            hrow[2 * lane + 1] = make_float4(sA.z, sB.z, sA.w, sB.w);
            const int gy = lo + r2;
            if (gy >= y0 && gy < y0 + SROWS) {
                float4* irow = (float4*)(img2 + r2 * ST);
                irow[2 * lane]     = make_float4(pv2.x, tv2.x, pv2.y, tv2.y);
                irow[2 * lane + 1] = make_float4(pv2.z, tv2.z, pv2.w, tv2.w);
                wsum += wmse_px4(pv2, tv2);
            }
        }
    }
    // wmse warp reduction pre-barrier (hidden under barrier-arrival skew)
    #pragma unroll
    for (int o = 16; o > 0; o >>= 1)
        wsum += __shfl_xor_sync(FULLM, wsum, o);
    if (lane == 0) wws[wid] = wsum;
    __syncthreads();     // hs/img + s_acc init visible (ONLY barrier)

    // ---- vertical sliding sums + span = sum |distP - distT| --------------
    const int x   = tid & 127;
    const int seg = tid >> 7;
    const int yb  = y0 + seg * 4;
    const int cx  = min(x + 4, IMG_W - 1) - max(x - 4, 0) + 1;

    float span = 0.0f;
    {
        float sA = 0.0f, sB = 0.0f;
        const int wlo = max(0, yb - 4), whi = min(IMG_H - 1, yb + 4);
        for (int yy = wlo; yy <= whi; ++yy) {
            const float2 h = hs2[(yy - lo) * ST + x];
            sA += h.x; sB += h.y;
        }
        #pragma unroll
        for (int k = 0; k < 4; ++k) {
            const int y  = yb + k;
            const int cy = min(y + 4, IMG_H - 1) - max(y - 4, 0) + 1;
            const float inv = __fdividef(1.0f, (float)(cx * cy));
            const float2 v = img2[(y - lo) * ST + x];
            const float da = v.x - sA * inv;
            const float db = v.y - sB * inv;
            span += fabsf(da - db);
            if (k < 3) {
                if (y + 5 < IMG_H) {
                    const float2 h = hs2[(y + 5 - lo) * ST + x];
                    sA += h.x; sB += h.y;
                }
                if (y - 4 >= 0) {
                    const float2 h = hs2[(y - 4 - lo) * ST + x];
                    sA -= h.x; sB -= h.y;
                }
            }
        }
    }
    // span warp reduction (fixed order -> deterministic)
    #pragma unroll
    for (int o = 16; o > 0; o >>= 1)
        span += __shfl_xor_sync(FULLM, span, o);
    if (lane == 0) wsp[wid] = span;

    // ---- packed warp merge in smem; last warp fires the global atomic -----
    if (lane == 0) {
        const unsigned long long sp_q =
            (unsigned long long)__float2ll_rn(span * (float)SPAN_SCALE);
        const unsigned long long wm_q =
            (unsigned long long)__float2ll_rn(wws[wid] * (float)WM_SCALE);
        const unsigned long long add =
            (1ULL << ARR_SH) | (sp_q << SPAN_SH) | wm_q;
        const unsigned long long prev = atomicAdd(&s_acc, add);
        if ((prev >> ARR_SH) == (unsigned long long)(NWARP - 1)) {
            // block totals arrived in the same transaction
            const unsigned long long tot = prev + add;
            const unsigned long long sp_blk = (tot >> SPAN_SH) & SPAN_MASK;
            const unsigned long long wm_blk = tot & WM_MASK;
            const unsigned long long gadd =
                (1ULL << ARR_SH) | (sp_blk << SPAN_SH) | wm_blk;
            const unsigned long long gprev = atomicAdd(&g_acc, gadd);
            if ((gprev >> ARR_SH) == (unsigned long long)(GBLK - 1)) {
                const unsigned long long gtot = gprev + gadd;
                st_rlx64(&g_acc, 0ULL);          // reset for next launch
                const double sp_tot =
                    (double)((gtot >> SPAN_SH) & SPAN_MASK) / SPAN_SCALE;
                const double wm_tot =
                    (double)(gtot & WM_MASK) / WM_SCALE;
                const double crps = sp_tot / (double)NPIX;
                const double wmse = wm_tot / (double)NPIX;
                out[0] = (float)(1e-4 * wmse + crps);
            }
        }
    }
    (void)wsp;
}

extern "C" void kernel_launch(void* const* d_in, const int* in_sizes, int n_in,
                              void* d_out, int out_size) {
    (void)in_sizes; (void)n_in; (void)out_size;
    const float* pred = (const float*)d_in[0];
    const float* tgt  = (const float*)d_in[1];
    float* out = (float*)d_out;

    fused_loss<<<GBLK, THREADS>>>(pred, tgt, out);
}